// round 8
// baseline (speedup 1.0000x reference)
#include <cuda_runtime.h>
#include <math.h>
#include <stdint.h>

#define CLAMP_V 10000.0f
#define EPS_V   1e-8f
#define C_DIM   1024
#define H_DIM   4
#define DH      256
#define S_MAX   18
#define SH_N    72          // S*H
#define SH_P    80          // padded to 5 m16 tiles
#define NCH     (C_DIM/32)  // 32 k-chunks in phase A

// ------------------------- device scratch (static, no allocs) ----------------
__device__ float    g_qp[S_MAX * C_DIM];
__device__ __align__(16) uint2 g_Bp[128 * SH_N * 4];   // [kg][sh][j] tf32 pairs (k,k+4)
__device__ float    g_Z[SH_N];
__device__ float    g_uT[C_DIM * SH_N];                // transposed accumulator [c][sh]
__device__ float    g_ubar[H_DIM * C_DIM];
__device__ float    g_obar[C_DIM];

// ------------------------------- helpers -------------------------------------
__device__ __forceinline__ float san(float v) {        // full sanitize (small kernels)
    if (!(v == v)) return 0.f;
    return fminf(fmaxf(v, -CLAMP_V), CLAMP_V);
}
__device__ __forceinline__ unsigned f2tf(float f) {
    unsigned r;
    asm("cvt.rna.tf32.f32 %0, %1;" : "=r"(r) : "f"(f));
    return r;
}
__device__ __forceinline__ void mma8(float d[4], const unsigned a[4], const unsigned b[2]) {
    asm volatile(
        "mma.sync.aligned.m16n8k8.row.col.f32.tf32.tf32.f32 "
        "{%0,%1,%2,%3},{%4,%5,%6,%7},{%8,%9},{%0,%1,%2,%3};\n"
        : "+f"(d[0]), "+f"(d[1]), "+f"(d[2]), "+f"(d[3])
        : "r"(a[0]), "r"(a[1]), "r"(a[2]), "r"(a[3]), "r"(b[0]), "r"(b[1]));
}
__device__ __forceinline__ void red2(float* p, float a, float b) {
    asm volatile("red.global.add.v2.f32 [%0], {%1, %2};" :: "l"(p), "f"(a), "f"(b) : "memory");
}
#define CPA16(dst, src) asm volatile("cp.async.cg.shared.global [%0], [%1], 16;" :: "r"(dst), "l"(src))
#define CPA_COMMIT()    asm volatile("cp.async.commit_group;")
#define CPA_WAIT1()     asm volatile("cp.async.wait_group 1;" ::: "memory")

__device__ __forceinline__ float block_reduce_sum(float v, float* red8) {
    #pragma unroll
    for (int o = 16; o > 0; o >>= 1) v += __shfl_xor_sync(0xffffffffu, v, o);
    int w = threadIdx.x >> 5, lane = threadIdx.x & 31;
    if (lane == 0) red8[w] = v;
    __syncthreads();
    float tot = 0.f;
    #pragma unroll
    for (int i = 0; i < 8; i++) tot += red8[i];
    return tot;
}

// ------------------------------- kernels -------------------------------------
__global__ void k_init() {
    int i = blockIdx.x * 256 + threadIdx.x;
    if (i < C_DIM * SH_N) g_uT[i] = 0.f;
    if (i < SH_N) g_Z[i] = 0.f;
}

// qp[s][j] = ( rmsnorm(seeds[s], w_nq) . Wq[j] + bq[j] ) / 16
__global__ void k_qp(const float* __restrict__ seeds, const float* __restrict__ w_nq,
                     const float* __restrict__ ipw, const float* __restrict__ ipb) {
    __shared__ __align__(16) float qrow[C_DIM];
    __shared__ float red8[8];
    int s = blockIdx.x, t = threadIdx.x;
    float ssq = 0.f;
    for (int i = t; i < C_DIM; i += 256) {
        float v = san(seeds[s * C_DIM + i]);
        qrow[i] = v;
        ssq += v * v;
    }
    __syncthreads();
    float tot = block_reduce_sum(ssq, red8);
    float inv = 1.f / (sqrtf(tot) * (1.0f / 32.0f) + EPS_V);
    __syncthreads();
    for (int i = t; i < C_DIM; i += 256) qrow[i] = w_nq[i] * qrow[i] * inv;
    __syncthreads();
    int j = blockIdx.y * 256 + t;
    const float4* wr = (const float4*)(ipw + (size_t)j * C_DIM);
    const float4* q4 = (const float4*)qrow;
    float acc = ipb[j];
    #pragma unroll 8
    for (int c = 0; c < C_DIM / 4; c++) {
        float4 a = wr[c]; float4 b = q4[c];
        acc += a.x * b.x + a.y * b.y + a.z * b.z + a.w * b.w;
    }
    g_qp[s * C_DIM + j] = acc * 0.0625f;
}

// B[sh][c] = w_nkv[c] * sum_d qp[s][h*DH+d] * Wk[h*DH+d][c]   -> packed tf32 pairs
__global__ void k_bmat(const float* __restrict__ ipw, const float* __restrict__ w_nkv) {
    __shared__ float qh[DH];
    int sh = blockIdx.x, t = threadIdx.x;
    int s = sh >> 2, h = sh & 3;
    qh[t] = g_qp[s * C_DIM + h * DH + t];   // blockDim = 256 == DH
    __syncthreads();
    int c = blockIdx.y * 256 + t;
    const float* wk = ipw + ((size_t)C_DIM + h * DH) * C_DIM + c;
    float acc = 0.f;
    #pragma unroll 8
    for (int d = 0; d < DH; d++) acc += qh[d] * wk[(size_t)d * C_DIM];
    float v = w_nkv[c] * acc;
    float v4 = __shfl_down_sync(0xffffffffu, v, 4);
    if ((c & 7) < 4) {
        int kg = c >> 3, j = c & 3;
        g_Bp[((size_t)kg * SH_N + sh) * 4 + j] = make_uint2(f2tf(v), f2tf(v4));
    }
}

// ---------------------------------------------------------------------------
// Fused kernel: 128 rows/block.
//   Phase A: scores (X @ B), rmsnorm inv, e = exp, weights w = e*inv stored to
//            shared Wt in packed MMA pair layout; Z partials via atomics.
//   Phase B: u_partial[c][sh] = X^T @ W using Wt, accumulated into g_uT via
//            vectorized red.global.add.v2.f32.
// Dynamic smem layout (110592 B total, 2 CTAs/SM):
//   [0,      69632)  XsB[2][64][136] f32   (phase B stage buffers)
//   [0,      36864)  XsA[2][128][36] f32   (phase A, overlaps XsB lifetime-disjoint)
//   [36864,  55296)  Bs [2][4][72][4] u2   (phase A)
//   [55296,  57600)  zs [8][72] f32        (phase A epilogue)
//   [69632, 110592)  Wt [16][80][4] u2     (written phase A epi, read phase B)
// ---------------------------------------------------------------------------
#define SMEM_FU 110592
__global__ void __launch_bounds__(256, 2) k_fused(const float* __restrict__ x, int N) {
    extern __shared__ __align__(16) char smem[];
    float (*XsA)[128][36]   = (float (*)[128][36])smem;
    uint2 (*Bs)[4][SH_N][4] = (uint2 (*)[4][SH_N][4])(smem + 36864);
    float (*zs)[SH_N]       = (float (*)[SH_N])(smem + 55296);
    float (*XsB)[64][136]   = (float (*)[64][136])smem;
    uint2 (*Wt)[SH_P][4]    = (uint2 (*)[SH_P][4])(smem + 69632);

    int t = threadIdx.x, w = t >> 5, lane = t & 31;
    int q = lane >> 2, j = lane & 3;
    size_t base = (size_t)blockIdx.x * 128;
    size_t lastRow = (size_t)N - 1;

    bool ok[2];
    ok[0] = (base + w * 16 + q) < (size_t)N;
    ok[1] = (base + w * 16 + q + 8) < (size_t)N;

    // ===================== Phase A: scores =====================
    float acc[9][4];
    #pragma unroll
    for (int n = 0; n < 9; n++)
        #pragma unroll
        for (int i = 0; i < 4; i++) acc[n][i] = 0.f;
    float ssq[2] = {0.f, 0.f};

    auto stageA = [&](int ch, int b) {
        unsigned xd = (unsigned)__cvta_generic_to_shared(&XsA[b][0][0]);
        int k0 = ch * 32;
        #pragma unroll
        for (int it = 0; it < 4; it++) {
            int idx = t + it * 256;
            int row = idx >> 3, seg = idx & 7;
            size_t gr = base + row; if (gr > lastRow) gr = lastRow;
            CPA16(xd + (unsigned)(row * 36 + seg * 4) * 4,
                  (const char*)(x + gr * C_DIM + k0 + seg * 4));
        }
        const char* src = (const char*)(g_Bp + (size_t)ch * 4 * SH_N * 4);
        unsigned bd = (unsigned)__cvta_generic_to_shared(&(*Bs)[0][0][0]) + b * 9216;
        CPA16(bd + t * 16, src + t * 16);
        CPA16(bd + (t + 256) * 16, src + (t + 256) * 16);
        if (t < 64) CPA16(bd + (t + 512) * 16, src + (t + 512) * 16);
    };

    stageA(0, 0);
    CPA_COMMIT();
    for (int ch = 0; ch < NCH; ch++) {
        int buf = ch & 1;
        if (ch + 1 < NCH) stageA(ch + 1, buf ^ 1);
        CPA_COMMIT();
        CPA_WAIT1();
        __syncthreads();
        #pragma unroll
        for (int ks = 0; ks < 4; ks++) {
            float xv[2][2];
            #pragma unroll
            for (int s = 0; s < 2; s++) {
                int r = w * 16 + s * 8 + q;
                xv[s][0] = XsA[buf][r][ks * 8 + j];
                xv[s][1] = XsA[buf][r][ks * 8 + j + 4];
                ssq[s] += xv[s][0] * xv[s][0] + xv[s][1] * xv[s][1];
            }
            unsigned a[4] = {f2tf(xv[0][0]), f2tf(xv[1][0]), f2tf(xv[0][1]), f2tf(xv[1][1])};
            #pragma unroll
            for (int nt = 0; nt < 9; nt++) {
                uint2 bb = Bs[buf][ks][nt * 8 + q][j];
                unsigned b[2] = {bb.x, bb.y};
                mma8(acc[nt], a, b);
            }
        }
        __syncthreads();
    }

    // per-row inverse rms
    float inv[2];
    #pragma unroll
    for (int s = 0; s < 2; s++) {
        float sv = ssq[s];
        sv += __shfl_xor_sync(0xffffffffu, sv, 1);
        sv += __shfl_xor_sync(0xffffffffu, sv, 2);
        inv[s] = 1.f / (sqrtf(sv) * (1.0f / 32.0f) + EPS_V);
    }

    // epilogue: e = exp(score); packed e*inv pairs into shared Wt; Z partials
    int g0 = w * 2, g1 = w * 2 + 1;
    int jj = q & 3;
    #pragma unroll
    for (int nt = 0; nt < 9; nt++) {
        int c0 = nt * 8 + 2 * j;
        float e00 = ok[0] ? __expf(acc[nt][0] * inv[0]) : 0.f;
        float e01 = ok[0] ? __expf(acc[nt][1] * inv[0]) : 0.f;
        float e10 = ok[1] ? __expf(acc[nt][2] * inv[1]) : 0.f;
        float e11 = ok[1] ? __expf(acc[nt][3] * inv[1]) : 0.f;
        float z0 = e00 + e10, z1 = e01 + e11;
        float w00 = e00 * inv[0], w01 = e01 * inv[0];
        float w10 = e10 * inv[1], w11 = e11 * inv[1];
        float p00 = __shfl_xor_sync(0xffffffffu, w00, 16);
        float p01 = __shfl_xor_sync(0xffffffffu, w01, 16);
        float p10 = __shfl_xor_sync(0xffffffffu, w10, 16);
        float p11 = __shfl_xor_sync(0xffffffffu, w11, 16);
        if (q < 4) {        // pair (row q, row q+4), col c0
            Wt[g0][c0][jj] = make_uint2(f2tf(w00), f2tf(p00));
            Wt[g1][c0][jj] = make_uint2(f2tf(w10), f2tf(p10));
        } else {            // pair (row q-4, row q), col c0+1
            Wt[g0][c0 + 1][jj] = make_uint2(f2tf(p01), f2tf(w01));
            Wt[g1][c0 + 1][jj] = make_uint2(f2tf(p11), f2tf(w11));
        }
        #pragma unroll
        for (int o = 4; o < 32; o <<= 1) {
            z0 += __shfl_xor_sync(0xffffffffu, z0, o);
            z1 += __shfl_xor_sync(0xffffffffu, z1, o);
        }
        if (q == 0) { zs[w][c0] = z0; zs[w][c0 + 1] = z1; }
    }
    __syncthreads();
    if (t < SH_N) {
        float z = 0.f;
        #pragma unroll
        for (int i = 0; i < 8; i++) z += zs[i][t];
        atomicAdd(&g_Z[t], z);
    }
    __syncthreads();   // zs reads done before phase B staging overwrites region

    // ===================== Phase B: u += X^T @ W =====================
    // stages s = cc*2 + rh : cols [cc*128, +128), rows [rh*64, +64)
    auto stageB = [&](int s, int b) {
        int cc = s >> 1, rh = s & 1;
        unsigned xd = (unsigned)__cvta_generic_to_shared(&XsB[b][0][0]);
        #pragma unroll
        for (int it = 0; it < 8; it++) {
            int idx = t + it * 256;
            int row = idx >> 5, seg = idx & 31;
            size_t gr = base + rh * 64 + row; if (gr > lastRow) gr = lastRow;
            CPA16(xd + (unsigned)(row * 136 + seg * 4) * 4,
                  (const char*)(x + gr * C_DIM + cc * 128 + seg * 4));
        }
    };

    float uacc[9][4];
    stageB(0, 0);
    CPA_COMMIT();
    for (int s = 0; s < 16; s++) {
        int buf = s & 1, cc = s >> 1, rh = s & 1;
        if (s + 1 < 16) stageB(s + 1, buf ^ 1);
        CPA_COMMIT();
        CPA_WAIT1();
        __syncthreads();
        if (rh == 0) {
            #pragma unroll
            for (int n = 0; n < 9; n++)
                #pragma unroll
                for (int i = 0; i < 4; i++) uacc[n][i] = 0.f;
        }
        #pragma unroll
        for (int kk = 0; kk < 8; kk++) {
            int r0 = kk * 8 + j;
            int cA = w * 16 + q;
            unsigned a[4] = { f2tf(XsB[buf][r0][cA]),     f2tf(XsB[buf][r0][cA + 8]),
                              f2tf(XsB[buf][r0 + 4][cA]), f2tf(XsB[buf][r0 + 4][cA + 8]) };
            int g = rh * 8 + kk;
            #pragma unroll
            for (int nt = 0; nt < 9; nt++) {
                uint2 bb = Wt[g][nt * 8 + q][j];
                unsigned b[2] = {bb.x, bb.y};
                mma8(uacc[nt], a, b);
            }
        }
        __syncthreads();
        if (rh == 1) {
            int cb = cc * 128 + w * 16;
            #pragma unroll
            for (int nt = 0; nt < 9; nt++) {
                int sh = nt * 8 + 2 * j;
                red2(&g_uT[(cb + q) * SH_N + sh],     uacc[nt][0], uacc[nt][1]);
                red2(&g_uT[(cb + q + 8) * SH_N + sh], uacc[nt][2], uacc[nt][3]);
            }
        }
    }
}

// ubar[h][c] = w_nkv[c] * mean_s ( uT[c][(s,h)] / Z[(s,h)] )
__global__ void k_ubar(const float* __restrict__ w_nkv, int S) {
    __shared__ float rzs[SH_N];
    int t = threadIdx.x;
    int i = blockIdx.x * 256 + t;
    if (t < SH_N) rzs[t] = 1.f / g_Z[t];
    __syncthreads();
    if (i >= H_DIM * C_DIM) return;
    int h = i >> 10, c = i & 1023;
    float s = 0.f;
    for (int si = 0; si < S; si++)
        s += g_uT[(size_t)c * SH_N + si * H_DIM + h] * rzs[si * H_DIM + h];
    g_ubar[i] = w_nkv[c] * s / (float)S;
}

// obar[j] = sum_c ubar[h][c] * Wv[2C+j][c] + bv[2C+j]
__global__ void k_obar(const float* __restrict__ ipw, const float* __restrict__ ipb) {
    __shared__ float red8[8];
    int j = blockIdx.x, t = threadIdx.x;
    int h = j >> 8;
    const float* wv = ipw + ((size_t)2 * C_DIM + j) * C_DIM;
    const float* ub = g_ubar + h * C_DIM;
    float acc = 0.f;
    for (int c = t; c < C_DIM; c += 256) acc += ub[c] * wv[c];
    float tot = block_reduce_sum(acc, red8);
    if (t == 0) g_obar[j] = tot + ipb[2 * C_DIM + j];
}

// out[c] = sanitize( sum_j obar[j] * Wout[c][j] + bout[c] )
__global__ void k_out(const float* __restrict__ opw, const float* __restrict__ opb,
                      float* __restrict__ out) {
    __shared__ float red8[8];
    int c = blockIdx.x, t = threadIdx.x;
    const float* wr = opw + (size_t)c * C_DIM;
    float acc = 0.f;
    for (int j = t; j < C_DIM; j += 256) acc += g_obar[j] * wr[j];
    float tot = block_reduce_sum(acc, red8);
    if (t == 0) out[c] = san(tot + opb[c]);
}

// ------------------------------- launcher ------------------------------------
extern "C" void kernel_launch(void* const* d_in, const int* in_sizes, int n_in,
                              void* d_out, int out_size) {
    const float* x     = (const float*)d_in[0];
    const float* seeds = (const float*)d_in[1];
    const float* w_nq  = (const float*)d_in[2];
    const float* w_nkv = (const float*)d_in[3];
    const float* ipw   = (const float*)d_in[4];
    const float* ipb   = (const float*)d_in[5];
    const float* opw   = (const float*)d_in[6];
    const float* opb   = (const float*)d_in[7];
    float* out = (float*)d_out;

    int N = in_sizes[0] / C_DIM;
    int S = in_sizes[1] / C_DIM;   // 18

    cudaFuncSetAttribute(k_fused, cudaFuncAttributeMaxDynamicSharedMemorySize, SMEM_FU);

    k_init<<<(C_DIM * SH_N + 255) / 256, 256>>>();
    k_qp<<<dim3(S, 4), 256>>>(seeds, w_nq, ipw, ipb);
    k_bmat<<<dim3(SH_N, 4), 256>>>(ipw, w_nkv);
    k_fused<<<(N + 127) / 128, 256, SMEM_FU>>>(x, N);
    k_ubar<<<(H_DIM * C_DIM + 255) / 256, 256>>>(w_nkv, S);
    k_obar<<<C_DIM, 256>>>(ipw, ipb);
    k_out<<<C_DIM, 256>>>(opw, opb, out);
}